// round 12
// baseline (speedup 1.0000x reference)
#include <cuda_runtime.h>

#define PI_F 3.14159265358979323846f

// ---------------- constant tables computed on-device from the small inputs ----
struct Params {
    float2 pair[136];   // (i<=j) upper-tri order: {a, b}, off-diag pre-doubled
    float  K[9];        // e = sum K[3r+s] * (1,C1,S1)_r * (1,C2,S2)_s
    float  W0, W1, b0, b1;
};
__device__ __align__(16) Params g_params;

// compile-time 16th-root twiddle table: W16[k] = (cos, sin)(2*pi*k/16)
__constant__ float2 W16[16] = {
    { 1.0000000000f,  0.0000000000f}, { 0.9238795325f,  0.3826834324f},
    { 0.7071067812f,  0.7071067812f}, { 0.3826834324f,  0.9238795325f},
    { 0.0000000000f,  1.0000000000f}, {-0.3826834324f,  0.9238795325f},
    {-0.7071067812f,  0.7071067812f}, {-0.9238795325f,  0.3826834324f},
    {-1.0000000000f,  0.0000000000f}, {-0.9238795325f, -0.3826834324f},
    {-0.7071067812f, -0.7071067812f}, {-0.3826834324f, -0.9238795325f},
    { 0.0000000000f, -1.0000000000f}, { 0.3826834324f, -0.9238795325f},
    { 0.7071067812f, -0.7071067812f}, { 0.9238795325f, -0.3826834324f}};

__device__ __forceinline__ float2 cmulf(float2 a, float2 b) {
    return make_float2(a.x * b.x - a.y * b.y, a.x * b.y + a.y * b.x);
}

// ---------------- setup: build U1 (16x16), U2 (4x4), fold into A/B/K ---------
__global__ void setup_kernel(const float* __restrict__ f1, const float* __restrict__ p1,
                             const float* __restrict__ f2, const float* __restrict__ p2,
                             const float* __restrict__ W, const float* __restrict__ bb) {
    __shared__ float2 U[256];
    __shared__ float2 V[256];
    __shared__ float2 U2s[16];
    __shared__ float2 V2s[16];

    const int t = threadIdx.x;
    const int r = t >> 4, c = t & 15;
    const float p1_0 = p1[0], p1_1 = p1[1];
    float sn_p11, cs_p11; __sincosf(0.5f * p1_1, &sn_p11, &cs_p11);

    // ---- U1: init = (fused RZ diag) * QFT ----
    {
        float ph = 0.0f;
        ph += (((r >> 3) & 1) ? 0.5f : -0.5f) * f1[0];
        ph += (((r >> 2) & 1) ? 0.5f : -0.5f) * f1[1];
        ph += (((r >> 1) & 1) ? 0.5f : -0.5f) * f1[2];
        ph += (((r     ) & 1) ? 0.5f : -0.5f) * f1[3];
        float sp, cp; __sincosf(ph, &sp, &cp);
        float2 w = W16[(r * c) & 15];
        U[t] = make_float2(0.25f * (w.x * cp - w.y * sp),
                           0.25f * (w.y * cp + w.x * sp));
    }
    __syncthreads();
    // Qdag @ U  (the only dense matmul) — twiddle conj from the constant table
    {
        float2 acc = make_float2(0.f, 0.f);
        #pragma unroll
        for (int k = 0; k < 16; ++k) {
            float2 w = W16[(r * k) & 15];      // conj(w) = (w.x, -w.y)
            float2 u = U[k * 16 + c];
            acc.x += w.x * u.x + w.y * u.y;
            acc.y += w.x * u.y - w.y * u.x;
        }
        V[t] = make_float2(0.25f * acc.x, 0.25f * acc.y);
    }
    __syncthreads();
    U[t] = V[t];
    __syncthreads();

    // g1: CRZ(p1_0) ctrl bit3, tgt bit2 (diag in-place)
    if ((r >> 3) & 1) {
        float ang = (((r >> 2) & 1) ? 0.5f : -0.5f) * p1_0;
        float sn, cs; __sincosf(ang, &sn, &cs);
        U[t] = cmulf(U[t], make_float2(cs, sn));
    }
    __syncthreads();
    // g2: X mask 8
    V[t] = U[((r ^ 8) << 4) | c]; __syncthreads(); U[t] = V[t]; __syncthreads();
    // g3: CRX(p1_1) ctrl bit3, tgt mask 4
    {
        float2 u = U[t];
        if ((r >> 3) & 1) {
            float2 v = U[((r ^ 4) << 4) | c];
            u = make_float2(cs_p11 * u.x + sn_p11 * v.y, cs_p11 * u.y - sn_p11 * v.x);
        }
        V[t] = u;
    }
    __syncthreads(); U[t] = V[t]; __syncthreads();
    // g4: X mask 8
    V[t] = U[((r ^ 8) << 4) | c]; __syncthreads(); U[t] = V[t]; __syncthreads();
    // g5: CRZ(p1_0) ctrl bit1, tgt bit0
    if ((r >> 1) & 1) {
        float ang = ((r & 1) ? 0.5f : -0.5f) * p1_0;
        float sn, cs; __sincosf(ang, &sn, &cs);
        U[t] = cmulf(U[t], make_float2(cs, sn));
    }
    __syncthreads();
    // g6: X mask 2
    V[t] = U[((r ^ 2) << 4) | c]; __syncthreads(); U[t] = V[t]; __syncthreads();
    // g7: CRX(p1_1) ctrl bit1, tgt mask 1
    {
        float2 u = U[t];
        if ((r >> 1) & 1) {
            float2 v = U[((r ^ 1) << 4) | c];
            u = make_float2(cs_p11 * u.x + sn_p11 * v.y, cs_p11 * u.y - sn_p11 * v.x);
        }
        V[t] = u;
    }
    __syncthreads(); U[t] = V[t]; __syncthreads();
    // g8: X mask 2
    V[t] = U[((r ^ 2) << 4) | c]; __syncthreads(); U[t] = V[t]; __syncthreads();

    // ---- pair table: A = Re(U1^H Z1 U1), B = Re(U1^H Z3 U1) ----
    if (r <= c) {
        const int i = r, j = c;
        float av = 0.f, bv = 0.f;
        #pragma unroll
        for (int m = 0; m < 16; ++m) {
            float2 ui = U[m * 16 + i], uj = U[m * 16 + j];
            float re = ui.x * uj.x + ui.y * uj.y;     // Re(conj(ui)*uj)
            float z1 = 1.f - 2.f * (float)((m >> 2) & 1);
            float z3 = 1.f - 2.f * (float)(m & 1);
            av += z1 * re;
            bv += z3 * re;
        }
        float w = (i < j) ? 2.f : 1.f;
        int idx = i * 16 - (i * (i - 1)) / 2 + (j - i);
        g_params.pair[idx] = make_float2(w * av, w * bv);
    }

    // ---- U2 (4x4) ----
    if (t < 16) {
        int r2 = t >> 2, c2 = t & 3;
        float ph = ((((r2 >> 1) & 1) ? 0.5f : -0.5f) * f2[0])
                 + ((( r2       & 1) ? 0.5f : -0.5f) * f2[1]);
        float sp, cp; __sincosf(ph, &sp, &cp);
        float2 w = W16[((r2 * c2) & 3) * 4];
        U2s[t] = make_float2(0.5f * (w.x * cp - w.y * sp),
                             0.5f * (w.y * cp + w.x * sp));
    }
    __syncthreads();
    if (t < 16) {  // Q2dag @ U2
        int r2 = t >> 2, c2 = t & 3;
        float2 acc = make_float2(0.f, 0.f);
        #pragma unroll
        for (int k = 0; k < 4; ++k) {
            float2 w = W16[((r2 * k) & 3) * 4];   // use conj(w)
            float2 u = U2s[k * 4 + c2];
            acc.x += w.x * u.x + w.y * u.y;
            acc.y += w.x * u.y - w.y * u.x;
        }
        V2s[t] = make_float2(0.5f * acc.x, 0.5f * acc.y);
    }
    __syncthreads();
    if (t < 16) {  // CRZ(p2[0]) ctrl bit1, tgt bit0
        int r2 = t >> 2;
        float2 u = V2s[t];
        if ((r2 >> 1) & 1) {
            float ang = ((r2 & 1) ? 0.5f : -0.5f) * p2[0];
            float sn, cs; __sincosf(ang, &sn, &cs);
            u = cmulf(u, make_float2(cs, sn));
        }
        U2s[t] = u;
    }
    __syncthreads();
    if (t < 16) {  // X mask 2
        int r2 = t >> 2, c2 = t & 3;
        V2s[t] = U2s[((r2 ^ 2) << 2) | c2];
    }
    __syncthreads();
    if (t < 16) {  // CRX(p2[1]) ctrl bit1, tgt mask 1
        int r2 = t >> 2, c2 = t & 3;
        float2 u = V2s[t];
        if ((r2 >> 1) & 1) {
            float sn, cs; __sincosf(0.5f * p2[1], &sn, &cs);
            float2 v = V2s[((r2 ^ 1) << 2) | c2];
            u = make_float2(cs * u.x + sn * v.y, cs * u.y - sn * v.x);
        }
        U2s[t] = u;
    }
    __syncthreads();
    if (t < 16) {  // X mask 2 (final U2 ends in V2s)
        int r2 = t >> 2, c2 = t & 3;
        V2s[t] = U2s[((r2 ^ 2) << 2) | c2];
    }
    __syncthreads();

    // ---- fold layer-2 into K ----
    if (t == 0) {
        float C[4][4];
        #pragma unroll
        for (int i = 0; i < 4; ++i)
            #pragma unroll
            for (int j = 0; j < 4; ++j) {
                float acc = 0.f;
                #pragma unroll
                for (int m = 0; m < 4; ++m) {
                    float2 ui = V2s[m * 4 + i], uj = V2s[m * 4 + j];
                    float z = 1.f - 2.f * (float)(m & 1);
                    acc += z * (ui.x * uj.x + ui.y * uj.y);
                }
                C[i][j] = acc;
            }
        float T[3][3];
        T[0][0] = C[0][0];            T[0][1] = 2.f * C[0][1];                   T[0][2] = C[1][1];
        T[1][0] = 2.f * C[0][2];      T[1][1] = 2.f * C[0][3] + 2.f * C[1][2];   T[1][2] = 2.f * C[1][3];
        T[2][0] = C[2][2];            T[2][1] = 2.f * C[2][3];                   T[2][2] = C[3][3];
        const float G[3][3] = {{0.5f, 0.5f, 0.f}, {0.f, 0.f, 0.5f}, {0.5f, -0.5f, 0.f}};
        #pragma unroll
        for (int rr = 0; rr < 3; ++rr)
            #pragma unroll
            for (int ss = 0; ss < 3; ++ss) {
                float k = 0.f;
                #pragma unroll
                for (int a = 0; a < 3; ++a)
                    #pragma unroll
                    for (int b2 = 0; b2 < 3; ++b2)
                        k += G[a][rr] * T[a][b2] * G[b2][ss];
                g_params.K[rr * 3 + ss] = k;
            }
        g_params.W0 = W[0];  g_params.W1 = W[1];
        g_params.b0 = bb[0]; g_params.b1 = bb[1];
    }
}

// ---- main kernel: 2 ADJACENT elements per thread, float4 coefficient loads --
__global__ __launch_bounds__(256) void qfcn_main(const float* __restrict__ x,
                                                 float4* __restrict__ out, int ngroups) {
    __shared__ float4 cpair4[68];   // two (a,b) pairs per float4
    __shared__ float  cK[13];
    {
        int t = threadIdx.x;
        if (t < 68) cpair4[t] = ((const float4*)g_params.pair)[t];
        if (t >= 68 && t < 81) cK[t - 68] = (&g_params.K[0])[t - 68];
    }
    __syncthreads();

    int g = blockIdx.x * 256 + threadIdx.x;
    if (g >= ngroups) return;

    // thread handles batch elements 2g and 2g+1: 32 contiguous floats
    const float4* px = (const float4*)x + (size_t)g * 8;
    float xa[16], xb[16];
    #pragma unroll
    for (int q = 0; q < 4; ++q) {
        float4 u = px[q];
        xa[q * 4 + 0] = u.x; xa[q * 4 + 1] = u.y; xa[q * 4 + 2] = u.z; xa[q * 4 + 3] = u.w;
    }
    #pragma unroll
    for (int q = 0; q < 4; ++q) {
        float4 u = px[4 + q];
        xb[q * 4 + 0] = u.x; xb[q * 4 + 1] = u.y; xb[q * 4 + 2] = u.z; xb[q * 4 + 3] = u.w;
    }

    // 2-way split accumulators per output for ILP (10 independent FMA chains)
    float e1a0 = 0.f, e1a1 = 0.f, e3a0 = 0.f, e3a1 = 0.f, ssa = 0.f;
    float e1b0 = 0.f, e1b1 = 0.f, e3b0 = 0.f, e3b1 = 0.f, ssb = 0.f;

    float4 f4 = cpair4[0];
    int idx = 0;
    #pragma unroll
    for (int i = 0; i < 16; ++i) {
        #pragma unroll
        for (int j = i; j < 16; ++j) {
            float ca, cb;
            if ((idx & 1) == 0) {
                f4 = cpair4[idx >> 1];
                ca = f4.x; cb = f4.y;
            } else {
                ca = f4.z; cb = f4.w;
            }
            float ta = xa[i] * xa[j];
            float tb = xb[i] * xb[j];
            if (idx & 1) {
                e1a0 = fmaf(ta, ca, e1a0);  e3a0 = fmaf(ta, cb, e3a0);
                e1b0 = fmaf(tb, ca, e1b0);  e3b0 = fmaf(tb, cb, e3b0);
            } else {
                e1a1 = fmaf(ta, ca, e1a1);  e3a1 = fmaf(ta, cb, e3a1);
                e1b1 = fmaf(tb, ca, e1b1);  e3b1 = fmaf(tb, cb, e3b1);
            }
            if (j == i) { ssa += ta; ssb += tb; }
            ++idx;
        }
    }
    float e1a = e1a0 + e1a1, e3a = e3a0 + e3a1;
    float e1b = e1b0 + e1b1, e3b = e3b0 + e3b1;

    const float K0 = cK[0], K1 = cK[1], K2 = cK[2];
    const float K3 = cK[3], K4 = cK[4], K5 = cK[5];
    const float K6 = cK[6], K7 = cK[7], K8 = cK[8];
    const float W0 = cK[9], W1 = cK[10], b0 = cK[11], b1 = cK[12];

    auto head = [&](float q1, float q3, float s) -> float2 {
        float inv = __fdividef(1.0f, s);
        float t1 = q1 * inv, t3 = q3 * inv;          // <Z_1>, <Z_3>  in [-1,1]
        float s1, c1, s2, c2;
        __sincosf(t1, &s1, &c1);
        __sincosf(t3, &s2, &c2);
        float e = K0 + K1 * c2 + K2 * s2
                + c1 * (K3 + K4 * c2 + K5 * s2)
                + s1 * (K6 + K7 * c2 + K8 * s2);
        return make_float2(fmaf(e, W0, b0), fmaf(e, W1, b1));
    };

    float2 ra = head(e1a, e3a, ssa);
    float2 rb = head(e1b, e3b, ssb);
    out[g] = make_float4(ra.x, ra.y, rb.x, rb.y);
}

extern "C" void kernel_launch(void* const* d_in, const int* in_sizes, int n_in,
                              void* d_out, int out_size) {
    const float* x  = (const float*)d_in[0];
    const float* f1 = (const float*)d_in[1];
    const float* p1 = (const float*)d_in[2];
    const float* f2 = (const float*)d_in[3];
    const float* p2 = (const float*)d_in[4];
    const float* W  = (const float*)d_in[5];
    const float* b  = (const float*)d_in[6];

    int B = in_sizes[0] / 16;
    int ngroups = B >> 1;

    setup_kernel<<<1, 256>>>(f1, p1, f2, p2, W, b);
    int blocks = (ngroups + 255) / 256;
    qfcn_main<<<blocks, 256>>>(x, (float4*)d_out, ngroups);
}

// round 13
// speedup vs baseline: 1.3401x; 1.3401x over previous
#include <cuda_runtime.h>

#define PI_F 3.14159265358979323846f

// ---------------- constant tables computed on-device from the small inputs ----
struct Params {
    float2 pair[136];   // (i<=j) upper-tri order: {a, b}, off-diag pre-doubled
    float  K[9];        // e = sum K[3r+s] * (1,C1,S1)_r * (1,C2,S2)_s
    float  W0, W1, b0, b1;
};
__device__ __align__(16) Params g_params;

// compile-time 16th-root twiddle table: W16[k] = (cos, sin)(2*pi*k/16)
__constant__ float2 W16[16] = {
    { 1.0000000000f,  0.0000000000f}, { 0.9238795325f,  0.3826834324f},
    { 0.7071067812f,  0.7071067812f}, { 0.3826834324f,  0.9238795325f},
    { 0.0000000000f,  1.0000000000f}, {-0.3826834324f,  0.9238795325f},
    {-0.7071067812f,  0.7071067812f}, {-0.9238795325f,  0.3826834324f},
    {-1.0000000000f,  0.0000000000f}, {-0.9238795325f, -0.3826834324f},
    {-0.7071067812f, -0.7071067812f}, {-0.3826834324f, -0.9238795325f},
    { 0.0000000000f, -1.0000000000f}, { 0.3826834324f, -0.9238795325f},
    { 0.7071067812f, -0.7071067812f}, { 0.9238795325f, -0.3826834324f}};

__device__ __forceinline__ float2 cmulf(float2 a, float2 b) {
    return make_float2(a.x * b.x - a.y * b.y, a.x * b.y + a.y * b.x);
}

// ---------------- setup: build U1 (16x16), U2 (4x4), fold into A/B/K ---------
__global__ void setup_kernel(const float* __restrict__ f1, const float* __restrict__ p1,
                             const float* __restrict__ f2, const float* __restrict__ p2,
                             const float* __restrict__ W, const float* __restrict__ bb) {
    __shared__ float2 U[256];
    __shared__ float2 V[256];
    __shared__ float2 U2s[16];
    __shared__ float2 V2s[16];

    const int t = threadIdx.x;
    const int r = t >> 4, c = t & 15;
    const float p1_0 = p1[0], p1_1 = p1[1];
    float sn_p11, cs_p11; __sincosf(0.5f * p1_1, &sn_p11, &cs_p11);

    // ---- U1: init = (fused RZ diag) * QFT ----
    {
        float ph = 0.0f;
        ph += (((r >> 3) & 1) ? 0.5f : -0.5f) * f1[0];
        ph += (((r >> 2) & 1) ? 0.5f : -0.5f) * f1[1];
        ph += (((r >> 1) & 1) ? 0.5f : -0.5f) * f1[2];
        ph += (((r     ) & 1) ? 0.5f : -0.5f) * f1[3];
        float sp, cp; __sincosf(ph, &sp, &cp);
        float2 w = W16[(r * c) & 15];
        U[t] = make_float2(0.25f * (w.x * cp - w.y * sp),
                           0.25f * (w.y * cp + w.x * sp));
    }
    __syncthreads();
    // Qdag @ U  (the only dense matmul) — twiddle conj from the constant table
    {
        float2 acc = make_float2(0.f, 0.f);
        #pragma unroll
        for (int k = 0; k < 16; ++k) {
            float2 w = W16[(r * k) & 15];      // conj(w) = (w.x, -w.y)
            float2 u = U[k * 16 + c];
            acc.x += w.x * u.x + w.y * u.y;
            acc.y += w.x * u.y - w.y * u.x;
        }
        V[t] = make_float2(0.25f * acc.x, 0.25f * acc.y);
    }
    __syncthreads();
    U[t] = V[t];
    __syncthreads();

    // g1: CRZ(p1_0) ctrl bit3, tgt bit2 (diag in-place)
    if ((r >> 3) & 1) {
        float ang = (((r >> 2) & 1) ? 0.5f : -0.5f) * p1_0;
        float sn, cs; __sincosf(ang, &sn, &cs);
        U[t] = cmulf(U[t], make_float2(cs, sn));
    }
    __syncthreads();
    // g2: X mask 8
    V[t] = U[((r ^ 8) << 4) | c]; __syncthreads(); U[t] = V[t]; __syncthreads();
    // g3: CRX(p1_1) ctrl bit3, tgt mask 4
    {
        float2 u = U[t];
        if ((r >> 3) & 1) {
            float2 v = U[((r ^ 4) << 4) | c];
            u = make_float2(cs_p11 * u.x + sn_p11 * v.y, cs_p11 * u.y - sn_p11 * v.x);
        }
        V[t] = u;
    }
    __syncthreads(); U[t] = V[t]; __syncthreads();
    // g4: X mask 8
    V[t] = U[((r ^ 8) << 4) | c]; __syncthreads(); U[t] = V[t]; __syncthreads();
    // g5: CRZ(p1_0) ctrl bit1, tgt bit0
    if ((r >> 1) & 1) {
        float ang = ((r & 1) ? 0.5f : -0.5f) * p1_0;
        float sn, cs; __sincosf(ang, &sn, &cs);
        U[t] = cmulf(U[t], make_float2(cs, sn));
    }
    __syncthreads();
    // g6: X mask 2
    V[t] = U[((r ^ 2) << 4) | c]; __syncthreads(); U[t] = V[t]; __syncthreads();
    // g7: CRX(p1_1) ctrl bit1, tgt mask 1
    {
        float2 u = U[t];
        if ((r >> 1) & 1) {
            float2 v = U[((r ^ 1) << 4) | c];
            u = make_float2(cs_p11 * u.x + sn_p11 * v.y, cs_p11 * u.y - sn_p11 * v.x);
        }
        V[t] = u;
    }
    __syncthreads(); U[t] = V[t]; __syncthreads();
    // g8: X mask 2
    V[t] = U[((r ^ 2) << 4) | c]; __syncthreads(); U[t] = V[t]; __syncthreads();

    // ---- pair table: A = Re(U1^H Z1 U1), B = Re(U1^H Z3 U1) ----
    if (r <= c) {
        const int i = r, j = c;
        float av = 0.f, bv = 0.f;
        #pragma unroll
        for (int m = 0; m < 16; ++m) {
            float2 ui = U[m * 16 + i], uj = U[m * 16 + j];
            float re = ui.x * uj.x + ui.y * uj.y;     // Re(conj(ui)*uj)
            float z1 = 1.f - 2.f * (float)((m >> 2) & 1);
            float z3 = 1.f - 2.f * (float)(m & 1);
            av += z1 * re;
            bv += z3 * re;
        }
        float w = (i < j) ? 2.f : 1.f;
        int idx = i * 16 - (i * (i - 1)) / 2 + (j - i);
        g_params.pair[idx] = make_float2(w * av, w * bv);
    }

    // ---- U2 (4x4) ----
    if (t < 16) {
        int r2 = t >> 2, c2 = t & 3;
        float ph = ((((r2 >> 1) & 1) ? 0.5f : -0.5f) * f2[0])
                 + ((( r2       & 1) ? 0.5f : -0.5f) * f2[1]);
        float sp, cp; __sincosf(ph, &sp, &cp);
        float2 w = W16[((r2 * c2) & 3) * 4];
        U2s[t] = make_float2(0.5f * (w.x * cp - w.y * sp),
                             0.5f * (w.y * cp + w.x * sp));
    }
    __syncthreads();
    if (t < 16) {  // Q2dag @ U2
        int r2 = t >> 2, c2 = t & 3;
        float2 acc = make_float2(0.f, 0.f);
        #pragma unroll
        for (int k = 0; k < 4; ++k) {
            float2 w = W16[((r2 * k) & 3) * 4];   // use conj(w)
            float2 u = U2s[k * 4 + c2];
            acc.x += w.x * u.x + w.y * u.y;
            acc.y += w.x * u.y - w.y * u.x;
        }
        V2s[t] = make_float2(0.5f * acc.x, 0.5f * acc.y);
    }
    __syncthreads();
    if (t < 16) {  // CRZ(p2[0]) ctrl bit1, tgt bit0
        int r2 = t >> 2;
        float2 u = V2s[t];
        if ((r2 >> 1) & 1) {
            float ang = ((r2 & 1) ? 0.5f : -0.5f) * p2[0];
            float sn, cs; __sincosf(ang, &sn, &cs);
            u = cmulf(u, make_float2(cs, sn));
        }
        U2s[t] = u;
    }
    __syncthreads();
    if (t < 16) {  // X mask 2
        int r2 = t >> 2, c2 = t & 3;
        V2s[t] = U2s[((r2 ^ 2) << 2) | c2];
    }
    __syncthreads();
    if (t < 16) {  // CRX(p2[1]) ctrl bit1, tgt mask 1
        int r2 = t >> 2, c2 = t & 3;
        float2 u = V2s[t];
        if ((r2 >> 1) & 1) {
            float sn, cs; __sincosf(0.5f * p2[1], &sn, &cs);
            float2 v = V2s[((r2 ^ 1) << 2) | c2];
            u = make_float2(cs * u.x + sn * v.y, cs * u.y - sn * v.x);
        }
        U2s[t] = u;
    }
    __syncthreads();
    if (t < 16) {  // X mask 2 (final U2 ends in V2s)
        int r2 = t >> 2, c2 = t & 3;
        V2s[t] = U2s[((r2 ^ 2) << 2) | c2];
    }
    __syncthreads();

    // ---- fold layer-2 into K ----
    if (t == 0) {
        float C[4][4];
        #pragma unroll
        for (int i = 0; i < 4; ++i)
            #pragma unroll
            for (int j = 0; j < 4; ++j) {
                float acc = 0.f;
                #pragma unroll
                for (int m = 0; m < 4; ++m) {
                    float2 ui = V2s[m * 4 + i], uj = V2s[m * 4 + j];
                    float z = 1.f - 2.f * (float)(m & 1);
                    acc += z * (ui.x * uj.x + ui.y * uj.y);
                }
                C[i][j] = acc;
            }
        float T[3][3];
        T[0][0] = C[0][0];            T[0][1] = 2.f * C[0][1];                   T[0][2] = C[1][1];
        T[1][0] = 2.f * C[0][2];      T[1][1] = 2.f * C[0][3] + 2.f * C[1][2];   T[1][2] = 2.f * C[1][3];
        T[2][0] = C[2][2];            T[2][1] = 2.f * C[2][3];                   T[2][2] = C[3][3];
        const float G[3][3] = {{0.5f, 0.5f, 0.f}, {0.f, 0.f, 0.5f}, {0.5f, -0.5f, 0.f}};
        #pragma unroll
        for (int rr = 0; rr < 3; ++rr)
            #pragma unroll
            for (int ss = 0; ss < 3; ++ss) {
                float k = 0.f;
                #pragma unroll
                for (int a = 0; a < 3; ++a)
                    #pragma unroll
                    for (int b2 = 0; b2 < 3; ++b2)
                        k += G[a][rr] * T[a][b2] * G[b2][ss];
                g_params.K[rr * 3 + ss] = k;
            }
        g_params.W0 = W[0];  g_params.W1 = W[1];
        g_params.b0 = bb[0]; g_params.b1 = bb[1];
    }
}

// ---- main kernel: 2 strided elements/thread, triangular row-accumulate form -
__global__ __launch_bounds__(256) void qfcn_main(const float* __restrict__ x,
                                                 float2* __restrict__ out, int half) {
    __shared__ float2 cpair[136];
    __shared__ float  cK[13];
    {
        int t = threadIdx.x;
        if (t < 136) cpair[t] = g_params.pair[t];
        if (t >= 136 && t < 149) cK[t - 136] = (&g_params.K[0])[t - 136];
    }
    __syncthreads();

    int gid = blockIdx.x * 256 + threadIdx.x;
    if (gid >= half) return;

    const float4* pa = (const float4*)x + (size_t)gid * 4;
    const float4* pb = (const float4*)x + ((size_t)gid + (size_t)half) * 4;

    float xa[16], xb[16];
    #pragma unroll
    for (int q = 0; q < 4; ++q) {
        float4 u = pa[q];
        xa[q * 4 + 0] = u.x; xa[q * 4 + 1] = u.y; xa[q * 4 + 2] = u.z; xa[q * 4 + 3] = u.w;
        float4 v = pb[q];
        xb[q * 4 + 0] = v.x; xb[q * 4 + 1] = v.y; xb[q * 4 + 2] = v.z; xb[q * 4 + 3] = v.w;
    }

    // triangular row-accumulate: e = sum_i x_i * (sum_{j>=i} C_ij x_j)
    float e1a = 0.f, e3a = 0.f, ssa = 0.f;
    float e1b = 0.f, e3b = 0.f, ssb = 0.f;

    int idx = 0;
    #pragma unroll
    for (int i = 0; i < 16; ++i) {
        float waa = 0.f, wba = 0.f;   // element-A row sums (A-table, B-table)
        float wab = 0.f, wbb = 0.f;   // element-B row sums
        #pragma unroll
        for (int j = i; j < 16; ++j) {
            float2 cc = cpair[idx];
            waa = fmaf(cc.x, xa[j], waa);
            wba = fmaf(cc.y, xa[j], wba);
            wab = fmaf(cc.x, xb[j], wab);
            wbb = fmaf(cc.y, xb[j], wbb);
            ++idx;
        }
        e1a = fmaf(xa[i], waa, e1a);  e3a = fmaf(xa[i], wba, e3a);
        e1b = fmaf(xb[i], wab, e1b);  e3b = fmaf(xb[i], wbb, e3b);
        ssa = fmaf(xa[i], xa[i], ssa);
        ssb = fmaf(xb[i], xb[i], ssb);
    }

    const float K0 = cK[0], K1 = cK[1], K2 = cK[2];
    const float K3 = cK[3], K4 = cK[4], K5 = cK[5];
    const float K6 = cK[6], K7 = cK[7], K8 = cK[8];
    const float W0 = cK[9], W1 = cK[10], b0 = cK[11], b1 = cK[12];

    auto head = [&](float q1, float q3, float s) -> float2 {
        float inv = __fdividef(1.0f, s);
        float t1 = q1 * inv, t3 = q3 * inv;          // <Z_1>, <Z_3>  in [-1,1]
        float s1, c1, s2, c2;
        __sincosf(t1, &s1, &c1);
        __sincosf(t3, &s2, &c2);
        float e = K0 + K1 * c2 + K2 * s2
                + c1 * (K3 + K4 * c2 + K5 * s2)
                + s1 * (K6 + K7 * c2 + K8 * s2);
        return make_float2(fmaf(e, W0, b0), fmaf(e, W1, b1));
    };

    out[gid]        = head(e1a, e3a, ssa);
    out[gid + half] = head(e1b, e3b, ssb);
}

extern "C" void kernel_launch(void* const* d_in, const int* in_sizes, int n_in,
                              void* d_out, int out_size) {
    const float* x  = (const float*)d_in[0];
    const float* f1 = (const float*)d_in[1];
    const float* p1 = (const float*)d_in[2];
    const float* f2 = (const float*)d_in[3];
    const float* p2 = (const float*)d_in[4];
    const float* W  = (const float*)d_in[5];
    const float* b  = (const float*)d_in[6];

    int B = in_sizes[0] / 16;
    int half = B >> 1;

    setup_kernel<<<1, 256>>>(f1, p1, f2, p2, W, b);
    int blocks = (half + 255) / 256;
    qfcn_main<<<blocks, 256>>>(x, (float2*)d_out, half);
}